// round 13
// baseline (speedup 1.0000x reference)
#include <cuda_runtime.h>

#define NN   5000
#define NE   8000
#define NDIR (2*NE)
#define NC   32
#define HD   64
#define NF   140
#define OPD  8
#define XND  148
#define CFD  24
#define POOLD 192
#define ROWLEN (NC*HD)   // 2048
#define STR  68          // padded smem row stride (conflict-free A-frag loads)

// per-half (128-thread) named barrier: halves advance independently
#define BARH(h) asm volatile("bar.sync %0, 128;" :: "r"(1 + (h)) : "memory")

typedef unsigned long long ull;

__device__ __forceinline__ ull f2pack(float x, float y) {
    ull r; asm("mov.b64 %0,{%1,%2};" : "=l"(r) : "f"(x), "f"(y)); return r;
}
__device__ __forceinline__ ull fma2(ull a, ull b, ull c) {
    ull d; asm("fma.rn.f32x2 %0,%1,%2,%3;" : "=l"(d) : "l"(a), "l"(b), "l"(c)); return d;
}
__device__ __forceinline__ float2 f2unpack(ull v) {
    float lo, hi; asm("mov.b64 {%0,%1},%2;" : "=f"(lo), "=f"(hi) : "l"(v));
    float2 r; r.x = lo; r.y = hi; return r;
}
__device__ __forceinline__ float4 relu4(float4 a) {
    return make_float4(fmaxf(a.x,0.f), fmaxf(a.y,0.f), fmaxf(a.z,0.f), fmaxf(a.w,0.f));
}
__device__ __forceinline__ unsigned tf32cvt(float x) {
    unsigned r; asm("cvt.rna.tf32.f32 %0,%1;" : "=r"(r) : "f"(x)); return r;
}
__device__ __forceinline__ float tf32f(float x) {
    return __uint_as_float(tf32cvt(x));
}
__device__ __forceinline__ float4 tf32f4(float4 a) {
    return make_float4(tf32f(a.x), tf32f(a.y), tf32f(a.z), tf32f(a.w));
}
__device__ __forceinline__ void mma_tf32(float* d, const unsigned* a,
                                         unsigned b0, unsigned b1) {
    asm volatile(
        "mma.sync.aligned.m16n8k8.row.col.f32.tf32.tf32.f32 "
        "{%0,%1,%2,%3},{%4,%5,%6,%7},{%8,%9},{%0,%1,%2,%3};"
        : "+f"(d[0]), "+f"(d[1]), "+f"(d[2]), "+f"(d[3])
        : "r"(a[0]), "r"(a[1]), "r"(a[2]), "r"(a[3]), "r"(b0), "r"(b1));
}

// ---------------- device scratch ---------------------------------------------
__device__ __align__(16) float g_xn[NN*XND];
__device__ __align__(16) float g_pernode[NN*HD];
__device__ __align__(16) float g_t1[NC*HD];
__device__ __align__(16) float g_t0[NC*HD];
__device__ __align__(16) float g_h1[(size_t)NN*ROWLEN];
// B-fragment tables in gmem (L1-resident, shared by all blocks)
__device__ __align__(16) unsigned g_fragF[3*4096];
__device__ __align__(16) unsigned g_fragL[4*4096];
__device__ int   g_deg[NN];
__device__ int   g_off[NN+1];
__device__ int   g_cur[NN];
__device__ int   g_adj[NDIR];
__device__ float g_pool[NC*POOLD];
__device__ int g_op64 = 1, g_ed64 = 1;  // monotone, input-determined

__device__ __forceinline__ int idx_at(const void* p, int i, int is64) {
    if (is64) return (int)((const long long*)p)[i];
    return ((const int*)p)[i];
}

__device__ __forceinline__ unsigned frag_of(const float* __restrict__ W, int i) {
    int j = i & 1, lane = (i >> 1) & 31, ks = (i >> 6) & 7, nt = (i >> 9) & 7;
    int g = lane >> 2, tg = lane & 3;
    return tf32cvt(W[(ks*8 + tg + j*4)*64 + nt*8 + g]);
}

// ---------------- pre: zero state + dtype detection ---------------------------
__global__ void k_pre(const void* opc, const void* ei) {
    int i = blockIdx.x * blockDim.x + threadIdx.x;
    if (i < NC*POOLD) g_pool[i] = 0.0f;
    if (i < NN) { g_deg[i] = 0; g_cur[i] = 0; }
    if (i < 2500) { if (((const unsigned*)opc)[2*i+1] != 0u) g_op64 = 0; }
    if (i < 8000) { if (((const unsigned*)ei )[2*i+1] != 0u) g_ed64 = 0; }
}

// ---------------- xn assembly + degree count ----------------------------------
__global__ void k_xn_deg(const float* __restrict__ nf, const void* __restrict__ opc,
                         const float* __restrict__ op_emb, const void* __restrict__ ei) {
    int idx = blockIdx.x * blockDim.x + threadIdx.x;
    if (idx < NN*XND) {
        int n = idx / XND, d = idx % XND;
        if (d < NF) g_xn[idx] = nf[n*NF + d];
        else {
            int op = idx_at(opc, n, g_op64);
            g_xn[idx] = op_emb[op*OPD + (d - NF)];
        }
    }
    if (idx < NE) {
        int a = idx_at(ei, 2*idx,   g_ed64);
        int b = idx_at(ei, 2*idx+1, g_ed64);
        atomicAdd(&g_deg[a], 1);
        atomicAdd(&g_deg[b], 1);
    }
}

// --------- scan (block 0) + cfg terms (blocks 1,2) + frag prep (3..30) --------
__global__ void k_scan_cfg(const float* __restrict__ cf, const float* __restrict__ ws0,
                           const float* __restrict__ wn0,
                           const float* __restrict__ ws, const float* __restrict__ wnn,
                           const float* __restrict__ skw) {
    int b = blockIdx.x;
    if (b == 0) {
        __shared__ int s[1024];
        int t = threadIdx.x;
        const int CH = 5;
        int base = t * CH;
        int v[CH]; int tot = 0;
        #pragma unroll
        for (int i = 0; i < CH; i++) {
            int idx = base + i;
            v[i] = (idx < NN) ? g_deg[idx] : 0;
            tot += v[i];
        }
        s[t] = tot; __syncthreads();
        for (int ofs = 1; ofs < 1024; ofs <<= 1) {
            int val = s[t];
            int add = (t >= ofs) ? s[t - ofs] : 0;
            __syncthreads();
            s[t] = val + add;
            __syncthreads();
        }
        int run = s[t] - tot;
        #pragma unroll
        for (int i = 0; i < CH; i++) {
            int idx = base + i;
            if (idx < NN) { g_off[idx] = run; run += v[i]; }
        }
        if (t == 1023) g_off[NN] = s[1023];
    } else if (b <= 2) {
        int idx = (b - 1) * 1024 + threadIdx.x;
        if (idx >= NC*HD) return;
        int c = idx >> 6, k = idx & 63;
        float s1 = 0.0f, s0v = 0.0f;
        #pragma unroll
        for (int d = 0; d < CFD; d++) {
            float cv = cf[c*CFD + d];
            float a  = ws0[(XND + d)*HD + k];
            float bq = wn0[(XND + d)*HD + k];
            s0v += cv * a;
            s1  += cv * (a + bq);
        }
        g_t0[idx] = s0v;
        g_t1[idx] = s1;
    } else if (b <= 14) {                     // g_fragF: 12 blocks x 1024
        int idx = (b - 3) * 1024 + threadIdx.x;
        int m = idx >> 12, i = idx & 4095;
        const float* W = (m == 0) ? ws : (m == 1) ? wnn : skw;
        g_fragF[idx] = frag_of(W, i);
    } else {                                   // g_fragL: 16 blocks x 1024
        int idx = (b - 15) * 1024 + threadIdx.x;
        int m = idx >> 12, i = idx & 4095;
        const float* W = (m == 0) ? (ws + HD*HD) : (m == 1) ? (wnn + HD*HD)
                        : (m == 2) ? (skw + HD*HD) : (skw + 2*HD*HD);
        g_fragL[idx] = frag_of(W, i);
    }
}

__global__ void k_fill(const void* __restrict__ ei) {
    int t = blockIdx.x * blockDim.x + threadIdx.x;
    if (t >= NE) return;
    int a = idx_at(ei, 2*t,   g_ed64);
    int b = idx_at(ei, 2*t+1, g_ed64);
    int pa = g_off[a] + atomicAdd(&g_cur[a], 1); g_adj[pa] = b;
    int pb = g_off[b] + atomicAdd(&g_cur[b], 1); g_adj[pb] = a;
}

// ---------------- layer-0 per-node GEMM (32-node tiles) ------------------------
__global__ void __launch_bounds__(256) k_pernode2(const float* __restrict__ ws0,
                                                  const float* __restrict__ wn0,
                                                  const float* __restrict__ b0) {
    extern __shared__ float sm[];
    float* ws0s = sm;
    float* wn0s = sm + 9472;
    float* xs   = sm + 18944;
    float* as_  = sm + 23680;
    int t = threadIdx.x;
    int tile = blockIdx.x;
    for (int i = t; i < XND*HD; i += 256) { ws0s[i] = ws0[i]; wn0s[i] = wn0[i]; }
    for (int i = t; i < 32*37; i += 256) {
        int s = i / 37, q = i % 37;
        int node = tile*32 + s;
        float4 xv = make_float4(0,0,0,0);
        float4 acc = make_float4(0,0,0,0);
        if (node < NN) {
            xv = ((const float4*)g_xn)[node*37 + q];
            int s0 = g_off[node], e0 = g_off[node+1];
            float inv = 1.0f / fmaxf((float)(e0 - s0), 1.0f);
            for (int j = s0; j < e0; j++) {
                float4 v = ((const float4*)g_xn)[g_adj[j]*37 + q];
                acc.x += v.x; acc.y += v.y; acc.z += v.z; acc.w += v.w;
            }
            acc.x *= inv; acc.y *= inv; acc.z *= inv; acc.w *= inv;
        }
        ((float4*)xs)[i] = xv;
        ((float4*)as_)[i] = acc;
    }
    __syncthreads();

    int rg = t >> 4, cg = t & 15;
    float4 b4 = *(const float4*)(b0 + cg*4);
    ull acc[2][2];
    acc[0][0] = f2pack(b4.x, b4.y); acc[0][1] = f2pack(b4.z, b4.w);
    acc[1][0] = acc[0][0];          acc[1][1] = acc[0][1];

    for (int dc = 0; dc < XND; dc += 4) {
        float4 x0 = *(const float4*)(xs  + (rg*2+0)*XND + dc);
        float4 x1 = *(const float4*)(xs  + (rg*2+1)*XND + dc);
        float4 a0 = *(const float4*)(as_ + (rg*2+0)*XND + dc);
        float4 a1 = *(const float4*)(as_ + (rg*2+1)*XND + dc);
        #pragma unroll
        for (int i = 0; i < 4; i++) {
            const ull* w1p = (const ull*)(ws0s + (dc+i)*HD + cg*4);
            const ull* w2p = (const ull*)(wn0s + (dc+i)*HD + cg*4);
            ull w1lo = w1p[0], w1hi = w1p[1];
            ull w2lo = w2p[0], w2hi = w2p[1];
            {
                float hx = ((const float*)&x0)[i], ax = ((const float*)&a0)[i];
                ull hb = f2pack(hx,hx), ab = f2pack(ax,ax);
                acc[0][0] = fma2(hb, w1lo, acc[0][0]);
                acc[0][0] = fma2(ab, w2lo, acc[0][0]);
                acc[0][1] = fma2(hb, w1hi, acc[0][1]);
                acc[0][1] = fma2(ab, w2hi, acc[0][1]);
            }
            {
                float hx = ((const float*)&x1)[i], ax = ((const float*)&a1)[i];
                ull hb = f2pack(hx,hx), ab = f2pack(ax,ax);
                acc[1][0] = fma2(hb, w1lo, acc[1][0]);
                acc[1][0] = fma2(ab, w2lo, acc[1][0]);
                acc[1][1] = fma2(hb, w1hi, acc[1][1]);
                acc[1][1] = fma2(ab, w2hi, acc[1][1]);
            }
        }
    }
    #pragma unroll
    for (int n = 0; n < 2; n++) {
        int node = tile*32 + rg*2 + n;
        if (node < NN) {
            float2 lo = f2unpack(acc[n][0]), hi = f2unpack(acc[n][1]);
            ((float4*)(g_pernode + node*HD))[cg] = make_float4(lo.x, lo.y, hi.x, hi.y);
        }
    }
}

// =============== layer 1 (tensor core): gmem B-frags, smaller smem ============
// smem: hsb[2x2176] asb[2x2176] t1s[2048] bds[64] bps[64] = 10880 floats
__global__ void __launch_bounds__(256) k_layer_first(
        float* __restrict__ hnew, const float* __restrict__ bias,
        const float* __restrict__ skb0) {
    extern __shared__ float sm[];
    float* hsb = sm;
    float* asb = sm + 4352;
    float* t1s = sm + 8704;
    float* bds = sm + 10752;
    float* bps = sm + 10816;
    int t = threadIdx.x;
    for (int i = t; i < NC*HD; i += 256) t1s[i] = g_t1[i];
    if (t < HD) { bds[t] = bias[t]; bps[t] = skb0[t]; }
    __syncthreads();

    const unsigned* __restrict__ wsF = g_fragF;
    const unsigned* __restrict__ wnF = g_fragF + 4096;
    const unsigned* __restrict__ spF = g_fragF + 8192;

    int half = t >> 7, wt = t & 127;
    int lane = t & 31, w = wt >> 5;
    int g = lane >> 2, tg = lane & 3;
    int rg = wt >> 4, kq = wt & 15;
    float* hs = hsb + half*2176;
    float* as = asb + half*2176;
    float4 t1r[4];
    #pragma unroll
    for (int m = 0; m < 4; m++) t1r[m] = ((const float4*)t1s)[(rg + 8*m)*16 + kq];

    float poolp[2][2][4];
    #pragma unroll
    for (int mt = 0; mt < 2; mt++)
        #pragma unroll
        for (int nt = 0; nt < 2; nt++)
            #pragma unroll
            for (int e = 0; e < 4; e++) poolp[mt][nt][e] = 0.0f;

    const float4* pern4 = (const float4*)g_pernode;

    for (int base = blockIdx.x*2; base < NN; base += gridDim.x*2) {
        int node = base + half;
        BARH(half);
        int s0 = g_off[node], e0 = g_off[node+1];
        float inv = 1.0f / fmaxf((float)(e0 - s0), 1.0f);
        float4 pown = pern4[node*16 + kq];
        #pragma unroll
        for (int m = 0; m < 4; m++) {
            int c = rg + 8*m;
            float4 tsel = t1r[m];
            if (e0 == s0) tsel = ((const float4*)g_t0)[c*16 + kq];  // rare path: gmem
            float4 r = relu4(make_float4(pown.x + tsel.x, pown.y + tsel.y,
                                         pown.z + tsel.z, pown.w + tsel.w));
            *(float4*)(hs + c*STR + kq*4) = tf32f4(r);
        }
        float4 ga[4];
        #pragma unroll
        for (int m = 0; m < 4; m++) ga[m] = make_float4(0,0,0,0);
        int j = s0;
        for (; j + 4 <= e0; j += 4) {
            int i0 = g_adj[j], i1 = g_adj[j+1], i2 = g_adj[j+2], i3 = g_adj[j+3];
            float4 p0 = pern4[i0*16 + kq];
            float4 p1 = pern4[i1*16 + kq];
            float4 p2 = pern4[i2*16 + kq];
            float4 p3 = pern4[i3*16 + kq];
            #pragma unroll
            for (int m = 0; m < 4; m++) {
                float4 tt = t1r[m];
                ga[m].x += fmaxf(p0.x + tt.x, 0.f) + fmaxf(p1.x + tt.x, 0.f)
                         + fmaxf(p2.x + tt.x, 0.f) + fmaxf(p3.x + tt.x, 0.f);
                ga[m].y += fmaxf(p0.y + tt.y, 0.f) + fmaxf(p1.y + tt.y, 0.f)
                         + fmaxf(p2.y + tt.y, 0.f) + fmaxf(p3.y + tt.y, 0.f);
                ga[m].z += fmaxf(p0.z + tt.z, 0.f) + fmaxf(p1.z + tt.z, 0.f)
                         + fmaxf(p2.z + tt.z, 0.f) + fmaxf(p3.z + tt.z, 0.f);
                ga[m].w += fmaxf(p0.w + tt.w, 0.f) + fmaxf(p1.w + tt.w, 0.f)
                         + fmaxf(p2.w + tt.w, 0.f) + fmaxf(p3.w + tt.w, 0.f);
            }
        }
        for (; j < e0; j++) {
            float4 p = pern4[g_adj[j]*16 + kq];
            #pragma unroll
            for (int m = 0; m < 4; m++) {
                float4 tt = t1r[m];
                ga[m].x += fmaxf(p.x + tt.x, 0.f);
                ga[m].y += fmaxf(p.y + tt.y, 0.f);
                ga[m].z += fmaxf(p.z + tt.z, 0.f);
                ga[m].w += fmaxf(p.w + tt.w, 0.f);
            }
        }
        #pragma unroll
        for (int m = 0; m < 4; m++) {
            int c = rg + 8*m;
            ga[m].x *= inv; ga[m].y *= inv; ga[m].z *= inv; ga[m].w *= inv;
            *(float4*)(as + c*STR + kq*4) = tf32f4(ga[m]);
        }
        BARH(half);

        float accd[2][2][4], acck[2][2][4];
        #pragma unroll
        for (int mt = 0; mt < 2; mt++)
            #pragma unroll
            for (int nt = 0; nt < 2; nt++)
                #pragma unroll
                for (int e = 0; e < 4; e++) { accd[mt][nt][e] = 0.f; acck[mt][nt][e] = 0.f; }
        #pragma unroll
        for (int ks = 0; ks < 8; ks++) {
            int k0 = ks*8;
            unsigned ah[2][4], aa[2][4];
            #pragma unroll
            for (int mt = 0; mt < 2; mt++) {
                int r0 = mt*16 + g;
                ah[mt][0] = __float_as_uint(hs[(r0  )*STR + k0 + tg]);
                ah[mt][1] = __float_as_uint(hs[(r0+8)*STR + k0 + tg]);
                ah[mt][2] = __float_as_uint(hs[(r0  )*STR + k0 + tg + 4]);
                ah[mt][3] = __float_as_uint(hs[(r0+8)*STR + k0 + tg + 4]);
                aa[mt][0] = __float_as_uint(as[(r0  )*STR + k0 + tg]);
                aa[mt][1] = __float_as_uint(as[(r0+8)*STR + k0 + tg]);
                aa[mt][2] = __float_as_uint(as[(r0  )*STR + k0 + tg + 4]);
                aa[mt][3] = __float_as_uint(as[(r0+8)*STR + k0 + tg + 4]);
            }
            #pragma unroll
            for (int nt = 0; nt < 2; nt++) {
                int fi = (((w*2 + nt)*8 + ks)*32 + lane)*2;
                uint2 bs = *(const uint2*)(wsF + fi);
                uint2 bn = *(const uint2*)(wnF + fi);
                uint2 bp = *(const uint2*)(spF + fi);
                #pragma unroll
                for (int mt = 0; mt < 2; mt++) {
                    mma_tf32(accd[mt][nt], ah[mt], bs.x, bs.y);
                    mma_tf32(accd[mt][nt], aa[mt], bn.x, bn.y);
                    mma_tf32(acck[mt][nt], ah[mt], bp.x, bp.y);
                }
            }
        }
        #pragma unroll
        for (int mt = 0; mt < 2; mt++)
            #pragma unroll
            for (int nt = 0; nt < 2; nt++) {
                int col = w*16 + nt*8 + 2*tg;
                float b0v = bds[col], b1v = bds[col+1];
                int r0 = mt*16 + g;
                float2 v0 = make_float2(fmaxf(accd[mt][nt][0] + b0v, 0.f),
                                        fmaxf(accd[mt][nt][1] + b1v, 0.f));
                float2 v1 = make_float2(fmaxf(accd[mt][nt][2] + b0v, 0.f),
                                        fmaxf(accd[mt][nt][3] + b1v, 0.f));
                *(float2*)(hnew + (size_t)node*ROWLEN + r0*HD + col) = v0;
                *(float2*)(hnew + (size_t)node*ROWLEN + (r0+8)*HD + col) = v1;
                float p0 = bps[col], p1 = bps[col+1];
                poolp[mt][nt][0] += fmaxf(acck[mt][nt][0] + p0, 0.f);
                poolp[mt][nt][1] += fmaxf(acck[mt][nt][1] + p1, 0.f);
                poolp[mt][nt][2] += fmaxf(acck[mt][nt][2] + p0, 0.f);
                poolp[mt][nt][3] += fmaxf(acck[mt][nt][3] + p1, 0.f);
            }
    }
    // pool merge (scratch = hsb; node loop complete for both halves)
    __syncthreads();
    if (half == 1) {
        #pragma unroll
        for (int mt = 0; mt < 2; mt++)
            #pragma unroll
            for (int nt = 0; nt < 2; nt++)
                #pragma unroll
                for (int e = 0; e < 4; e++)
                    hsb[wt*16 + (mt*2+nt)*4 + e] = poolp[mt][nt][e];
    }
    __syncthreads();
    if (half == 0) {
        #pragma unroll
        for (int mt = 0; mt < 2; mt++)
            #pragma unroll
            for (int nt = 0; nt < 2; nt++) {
                int col = w*16 + nt*8 + 2*tg;
                #pragma unroll
                for (int e = 0; e < 4; e++) {
                    float v = poolp[mt][nt][e] + hsb[wt*16 + (mt*2+nt)*4 + e];
                    int c = mt*16 + g + ((e >= 2) ? 8 : 0);
                    int cc = col + (e & 1);
                    atomicAdd(&g_pool[c*POOLD + 0*HD + cc], v);
                }
            }
    }
}

// =============== layer 2 (tensor core): gmem B-frags, high occupancy ==========
// smem: hsb[2x2176] asb[2x2176] bds[64] bps[64] bos[64] = 8896 floats
__global__ void __launch_bounds__(256) k_layer_last(
        const float* __restrict__ hold, const float* __restrict__ bias,
        const float* __restrict__ skbp, const float* __restrict__ skbo) {
    extern __shared__ float sm[];
    float* hsb = sm;
    float* asb = sm + 4352;
    float* bds = sm + 8704;
    float* bps = sm + 8768;
    float* bos = sm + 8832;
    int t = threadIdx.x;
    if (t < HD) { bds[t] = bias[t]; bps[t] = skbp[t]; bos[t] = skbo[t]; }
    __syncthreads();

    const unsigned* __restrict__ wsF = g_fragL;
    const unsigned* __restrict__ wnF = g_fragL + 4096;
    const unsigned* __restrict__ spF = g_fragL + 8192;
    const unsigned* __restrict__ soF = g_fragL + 12288;

    int half = t >> 7, wt = t & 127;
    int lane = t & 31, w = wt >> 5;
    int g = lane >> 2, tg = lane & 3;
    int rg = wt >> 4, kq = wt & 15;
    float* hs = hsb + half*2176;
    float* as = asb + half*2176;

    float poolp[2][2][4], poolo[2][2][4];
    #pragma unroll
    for (int mt = 0; mt < 2; mt++)
        #pragma unroll
        for (int nt = 0; nt < 2; nt++)
            #pragma unroll
            for (int e = 0; e < 4; e++) { poolp[mt][nt][e] = 0.f; poolo[mt][nt][e] = 0.f; }

    for (int base = blockIdx.x*2; base < NN; base += gridDim.x*2) {
        int node = base + half;
        BARH(half);
        int s0 = g_off[node], e0 = g_off[node+1];
        float inv = 1.0f / fmaxf((float)(e0 - s0), 1.0f);
        const float4* own = (const float4*)(hold + (size_t)node*ROWLEN);
        float4 hv[4];
        #pragma unroll
        for (int m = 0; m < 4; m++) hv[m] = own[(rg + 8*m)*16 + kq];
        #pragma unroll
        for (int m = 0; m < 4; m++)
            *(float4*)(hs + (rg + 8*m)*STR + kq*4) = tf32f4(hv[m]);
        float4 am[4];
        #pragma unroll
        for (int m = 0; m < 4; m++) am[m] = make_float4(0,0,0,0);
        int j = s0;
        for (; j + 4 <= e0; j += 4) {
            int i0 = g_adj[j], i1 = g_adj[j+1], i2 = g_adj[j+2], i3 = g_adj[j+3];
            const float4* r0 = (const float4*)(hold + (size_t)i0*ROWLEN);
            const float4* r1 = (const float4*)(hold + (size_t)i1*ROWLEN);
            const float4* r2 = (const float4*)(hold + (size_t)i2*ROWLEN);
            const float4* r3 = (const float4*)(hold + (size_t)i3*ROWLEN);
            #pragma unroll
            for (int m = 0; m < 4; m++) {
                int ofs = (rg + 8*m)*16 + kq;
                float4 v0 = r0[ofs], v1 = r1[ofs], v2 = r2[ofs], v3 = r3[ofs];
                am[m].x += (v0.x + v1.x) + (v2.x + v3.x);
                am[m].y += (v0.y + v1.y) + (v2.y + v3.y);
                am[m].z += (v0.z + v1.z) + (v2.z + v3.z);
                am[m].w += (v0.w + v1.w) + (v2.w + v3.w);
            }
        }
        for (; j < e0; j++) {
            const float4* row = (const float4*)(hold + (size_t)g_adj[j]*ROWLEN);
            #pragma unroll
            for (int m = 0; m < 4; m++) {
                float4 v = row[(rg + 8*m)*16 + kq];
                am[m].x += v.x; am[m].y += v.y; am[m].z += v.z; am[m].w += v.w;
            }
        }
        #pragma unroll
        for (int m = 0; m < 4; m++) {
            int c = rg + 8*m;
            am[m].x *= inv; am[m].y *= inv; am[m].z *= inv; am[m].w *= inv;
            *(float4*)(as + c*STR + kq*4) = tf32f4(am[m]);
        }
        BARH(half);

        float accd[2][2][4], acck[2][2][4];
        #pragma unroll
        for (int mt = 0; mt < 2; mt++)
            #pragma unroll
            for (int nt = 0; nt < 2; nt++)
                #pragma unroll
                for (int e = 0; e < 4; e++) { accd[mt][nt][e] = 0.f; acck[mt][nt][e] = 0.f; }
        #pragma unroll
        for (int ks = 0; ks < 8; ks++) {
            int k0 = ks*8;
            unsigned ah[2][4], aa[2][4];
            #pragma unroll
            for (int mt = 0; mt < 2; mt++) {
                int r0 = mt*16 + g;
                ah[mt][0] = __float_as_uint(hs[(r0  )*STR + k0 + tg]);
                ah[mt][1] = __float_as_uint(hs[(r0+8)*STR + k0 + tg]);
                ah[mt][2] = __float_as_uint(hs[(r0  )*STR + k0 + tg + 4]);
                ah[mt][3] = __float_as_uint(hs[(r0+8)*STR + k0 + tg + 4]);
                aa[mt][0] = __float_as_uint(as[(r0  )*STR + k0 + tg]);
                aa[mt][1] = __float_as_uint(as[(r0+8)*STR + k0 + tg]);
                aa[mt][2] = __float_as_uint(as[(r0  )*STR + k0 + tg + 4]);
                aa[mt][3] = __float_as_uint(as[(r0+8)*STR + k0 + tg + 4]);
            }
            #pragma unroll
            for (int nt = 0; nt < 2; nt++) {
                int fi = (((w*2 + nt)*8 + ks)*32 + lane)*2;
                uint2 bs = *(const uint2*)(wsF + fi);
                uint2 bn = *(const uint2*)(wnF + fi);
                uint2 bp = *(const uint2*)(spF + fi);
                #pragma unroll
                for (int mt = 0; mt < 2; mt++) {
                    mma_tf32(accd[mt][nt], ah[mt], bs.x, bs.y);
                    mma_tf32(accd[mt][nt], aa[mt], bn.x, bn.y);
                    mma_tf32(acck[mt][nt], ah[mt], bp.x, bp.y);
                }
            }
        }
        BARH(half);
        #pragma unroll
        for (int mt = 0; mt < 2; mt++)
            #pragma unroll
            for (int nt = 0; nt < 2; nt++) {
                int col = w*16 + nt*8 + 2*tg;
                float b0v = bds[col], b1v = bds[col+1];
                int r0 = mt*16 + g;
                *(float2*)(hs + r0*STR + col) =
                    make_float2(tf32f(fmaxf(accd[mt][nt][0] + b0v, 0.f)),
                                tf32f(fmaxf(accd[mt][nt][1] + b1v, 0.f)));
                *(float2*)(hs + (r0+8)*STR + col) =
                    make_float2(tf32f(fmaxf(accd[mt][nt][2] + b0v, 0.f)),
                                tf32f(fmaxf(accd[mt][nt][3] + b1v, 0.f)));
                float p0 = bps[col], p1 = bps[col+1];
                poolp[mt][nt][0] += fmaxf(acck[mt][nt][0] + p0, 0.f);
                poolp[mt][nt][1] += fmaxf(acck[mt][nt][1] + p1, 0.f);
                poolp[mt][nt][2] += fmaxf(acck[mt][nt][2] + p0, 0.f);
                poolp[mt][nt][3] += fmaxf(acck[mt][nt][3] + p1, 0.f);
            }
        BARH(half);

        float acco[2][2][4];
        #pragma unroll
        for (int mt = 0; mt < 2; mt++)
            #pragma unroll
            for (int nt = 0; nt < 2; nt++)
                #pragma unroll
                for (int e = 0; e < 4; e++) acco[mt][nt][e] = 0.f;
        #pragma unroll
        for (int ks = 0; ks < 8; ks++) {
            int k0 = ks*8;
            unsigned ah[2][4];
            #pragma unroll
            for (int mt = 0; mt < 2; mt++) {
                int r0 = mt*16 + g;
                ah[mt][0] = __float_as_uint(hs[(r0  )*STR + k0 + tg]);
                ah[mt][1] = __float_as_uint(hs[(r0+8)*STR + k0 + tg]);
                ah[mt][2] = __float_as_uint(hs[(r0  )*STR + k0 + tg + 4]);
                ah[mt][3] = __float_as_uint(hs[(r0+8)*STR + k0 + tg + 4]);
            }
            #pragma unroll
            for (int nt = 0; nt < 2; nt++) {
                int fi = (((w*2 + nt)*8 + ks)*32 + lane)*2;
                uint2 bo = *(const uint2*)(soF + fi);
                #pragma unroll
                for (int mt = 0; mt < 2; mt++)
                    mma_tf32(acco[mt][nt], ah[mt], bo.x, bo.y);
            }
        }
        #pragma unroll
        for (int mt = 0; mt < 2; mt++)
            #pragma unroll
            for (int nt = 0; nt < 2; nt++) {
                int col = w*16 + nt*8 + 2*tg;
                float p0 = bos[col], p1 = bos[col+1];
                poolo[mt][nt][0] += fmaxf(acco[mt][nt][0] + p0, 0.f);
                poolo[mt][nt][1] += fmaxf(acco[mt][nt][1] + p1, 0.f);
                poolo[mt][nt][2] += fmaxf(acco[mt][nt][2] + p0, 0.f);
                poolo[mt][nt][3] += fmaxf(acco[mt][nt][3] + p1, 0.f);
            }
    }
    // pool merge + atomics (scratch = hsb)
    __syncthreads();
    if (half == 1) {
        #pragma unroll
        for (int mt = 0; mt < 2; mt++)
            #pragma unroll
            for (int nt = 0; nt < 2; nt++)
                #pragma unroll
                for (int e = 0; e < 4; e++) {
                    hsb[wt*32 + (mt*2+nt)*4 + e] = poolp[mt][nt][e];
                    hsb[wt*32 + 16 + (mt*2+nt)*4 + e] = poolo[mt][nt][e];
                }
    }
    __syncthreads();
    if (half == 0) {
        #pragma unroll
        for (int mt = 0; mt < 2; mt++)
            #pragma unroll
            for (int nt = 0; nt < 2; nt++) {
                int col = w*16 + nt*8 + 2*tg;
                #pragma unroll
                for (int e = 0; e < 4; e++) {
                    int c = mt*16 + g + ((e >= 2) ? 8 : 0);
                    int cc = col + (e & 1);
                    float v = poolp[mt][nt][e] + hsb[wt*32 + (mt*2+nt)*4 + e];
                    atomicAdd(&g_pool[c*POOLD + 1*HD + cc], v);
                    float u = poolo[mt][nt][e] + hsb[wt*32 + 16 + (mt*2+nt)*4 + e];
                    atomicAdd(&g_pool[c*POOLD + 2*HD + cc], u);
                }
            }
    }
}

// ---------------- final MLP ----------------------------------------------------
__global__ void k_mlp(const float* __restrict__ p1w, const float* __restrict__ p1b,
                      const float* __restrict__ p2w, const float* __restrict__ p2b,
                      const float* __restrict__ p3w, const float* __restrict__ p3b,
                      float* __restrict__ out) {
    int c = blockIdx.x;
    int t = threadIdx.x;  // 128
    __shared__ float pr[POOLD], y1[128], y2[64];
    for (int i = t; i < POOLD; i += 128) pr[i] = g_pool[c*POOLD + i];
    __syncthreads();
    float s = p1b[t];
    #pragma unroll 4
    for (int d = 0; d < POOLD; d++) s += pr[d] * p1w[d*128 + t];
    y1[t] = fmaxf(s, 0.f);
    __syncthreads();
    if (t < 64) {
        float s2 = p2b[t];
        #pragma unroll 4
        for (int d = 0; d < 128; d++) s2 += y1[d] * p2w[d*64 + t];
        y2[t] = fmaxf(s2, 0.f);
    }
    __syncthreads();
    if (t == 0) {
        float s3 = p3b[0];
        for (int d = 0; d < 64; d++) s3 += y2[d] * p3w[d];
        out[c] = s3;
    }
}

// ---------------- launch -------------------------------------------------------
extern "C" void kernel_launch(void* const* d_in, const int* in_sizes, int n_in,
                              void* d_out, int out_size) {
    const float* nf     = (const float*)d_in[0];
    const void*  opc    = d_in[1];
    const void*  ei     = d_in[2];
    const float* cf     = (const float*)d_in[3];
    const float* op_emb = (const float*)d_in[4];
    const float* ws0    = (const float*)d_in[5];
    const float* wn0    = (const float*)d_in[6];
    const float* b0     = (const float*)d_in[7];
    const float* ws     = (const float*)d_in[8];
    const float* wnn    = (const float*)d_in[9];
    const float* bb     = (const float*)d_in[10];
    const float* skw    = (const float*)d_in[11];
    const float* skb    = (const float*)d_in[12];
    const float* p1w    = (const float*)d_in[13];
    const float* p1b    = (const float*)d_in[14];
    const float* p2w    = (const float*)d_in[15];
    const float* p2b    = (const float*)d_in[16];
    const float* p3w    = (const float*)d_in[17];
    const float* p3b    = (const float*)d_in[18];
    float* out = (float*)d_out;

    const int SMEM_LF = 10880 * (int)sizeof(float);  // 43520 B -> 5 blocks/SM
    const int SMEM_LL = 8896  * (int)sizeof(float);  // 35584 B -> 6 blocks/SM
    const int SMEM_PN = 28416 * (int)sizeof(float);  // 113664 B
    cudaFuncSetAttribute(k_layer_first,
                         cudaFuncAttributeMaxDynamicSharedMemorySize, SMEM_LF);
    cudaFuncSetAttribute(k_layer_last,
                         cudaFuncAttributeMaxDynamicSharedMemorySize, SMEM_LL);
    cudaFuncSetAttribute(k_pernode2,
                         cudaFuncAttributeMaxDynamicSharedMemorySize, SMEM_PN);

    float* ph1 = nullptr;
    cudaGetSymbolAddress((void**)&ph1, g_h1);

    k_pre<<<32, 256>>>(opc, ei);
    k_xn_deg<<<(NN*XND + 255)/256, 256>>>(nf, opc, op_emb, ei);
    k_scan_cfg<<<31, 1024>>>(cf, ws0, wn0, ws, wnn, skw);
    k_fill<<<(NE + 255)/256, 256>>>(ei);
    k_pernode2<<<157, 256, SMEM_PN>>>(ws0, wn0, b0);
    k_layer_first<<<740, 256, SMEM_LF>>>(ph1, bb, skb);
    k_layer_last<<<888, 256, SMEM_LL>>>(ph1, bb + HD, skb + HD, skb + 2*HD);
    k_mlp<<<32, 128>>>(p1w, p1b, p2w, p2b, p3w, p3b, out);
}

// round 14
// speedup vs baseline: 1.0801x; 1.0801x over previous
#include <cuda_runtime.h>

#define NN   5000
#define NE   8000
#define NDIR (2*NE)
#define NC   32
#define HD   64
#define NF   140
#define OPD  8
#define XND  148
#define CFD  24
#define POOLD 192
#define ROWLEN (NC*HD)   // 2048
#define STR  68          // padded smem row stride (conflict-free A-frag loads)

// per-half (128-thread) named barrier: halves advance independently
#define BARH(h) asm volatile("bar.sync %0, 128;" :: "r"(1 + (h)) : "memory")

typedef unsigned long long ull;

__device__ __forceinline__ ull f2pack(float x, float y) {
    ull r; asm("mov.b64 %0,{%1,%2};" : "=l"(r) : "f"(x), "f"(y)); return r;
}
__device__ __forceinline__ ull fma2(ull a, ull b, ull c) {
    ull d; asm("fma.rn.f32x2 %0,%1,%2,%3;" : "=l"(d) : "l"(a), "l"(b), "l"(c)); return d;
}
__device__ __forceinline__ float2 f2unpack(ull v) {
    float lo, hi; asm("mov.b64 {%0,%1},%2;" : "=f"(lo), "=f"(hi) : "l"(v));
    float2 r; r.x = lo; r.y = hi; return r;
}
__device__ __forceinline__ float4 relu4(float4 a) {
    return make_float4(fmaxf(a.x,0.f), fmaxf(a.y,0.f), fmaxf(a.z,0.f), fmaxf(a.w,0.f));
}
__device__ __forceinline__ unsigned tf32cvt(float x) {
    unsigned r; asm("cvt.rna.tf32.f32 %0,%1;" : "=r"(r) : "f"(x)); return r;
}
__device__ __forceinline__ float tf32f(float x) {
    return __uint_as_float(tf32cvt(x));
}
__device__ __forceinline__ float4 tf32f4(float4 a) {
    return make_float4(tf32f(a.x), tf32f(a.y), tf32f(a.z), tf32f(a.w));
}
__device__ __forceinline__ void mma_tf32(float* d, const unsigned* a,
                                         unsigned b0, unsigned b1) {
    asm volatile(
        "mma.sync.aligned.m16n8k8.row.col.f32.tf32.tf32.f32 "
        "{%0,%1,%2,%3},{%4,%5,%6,%7},{%8,%9},{%0,%1,%2,%3};"
        : "+f"(d[0]), "+f"(d[1]), "+f"(d[2]), "+f"(d[3])
        : "r"(a[0]), "r"(a[1]), "r"(a[2]), "r"(a[3]), "r"(b0), "r"(b1));
}

// ---------------- device scratch ---------------------------------------------
__device__ __align__(16) float g_xn[NN*XND];
__device__ __align__(16) float g_pernode[NN*HD];
__device__ __align__(16) float g_t1[NC*HD];
__device__ __align__(16) float g_t0[NC*HD];
__device__ __align__(16) float g_h1[(size_t)NN*ROWLEN];
// B-fragment tables in gmem (L1-resident, shared by all blocks)
__device__ __align__(16) unsigned g_fragF[3*4096];
__device__ __align__(16) unsigned g_fragL[4*4096];
__device__ int   g_deg[NN];
__device__ int   g_off[NN+1];
__device__ int   g_cur[NN];
__device__ int   g_adj[NDIR];
__device__ float g_pool[NC*POOLD];
__device__ int g_op64 = 1, g_ed64 = 1;  // monotone, input-determined

__device__ __forceinline__ int idx_at(const void* p, int i, int is64) {
    if (is64) return (int)((const long long*)p)[i];
    return ((const int*)p)[i];
}

__device__ __forceinline__ unsigned frag_of(const float* __restrict__ W, int i) {
    int j = i & 1, lane = (i >> 1) & 31, ks = (i >> 6) & 7, nt = (i >> 9) & 7;
    int g = lane >> 2, tg = lane & 3;
    return tf32cvt(W[(ks*8 + tg + j*4)*64 + nt*8 + g]);
}

// ---------------- pre: zero state + dtype detection ---------------------------
__global__ void k_pre(const void* opc, const void* ei) {
    int i = blockIdx.x * blockDim.x + threadIdx.x;
    if (i < NC*POOLD) g_pool[i] = 0.0f;
    if (i < NN) { g_deg[i] = 0; g_cur[i] = 0; }
    if (i < 2500) { if (((const unsigned*)opc)[2*i+1] != 0u) g_op64 = 0; }
    if (i < 8000) { if (((const unsigned*)ei )[2*i+1] != 0u) g_ed64 = 0; }
}

// ---------------- xn assembly + degree count ----------------------------------
__global__ void k_xn_deg(const float* __restrict__ nf, const void* __restrict__ opc,
                         const float* __restrict__ op_emb, const void* __restrict__ ei) {
    int idx = blockIdx.x * blockDim.x + threadIdx.x;
    if (idx < NN*XND) {
        int n = idx / XND, d = idx % XND;
        if (d < NF) g_xn[idx] = nf[n*NF + d];
        else {
            int op = idx_at(opc, n, g_op64);
            g_xn[idx] = op_emb[op*OPD + (d - NF)];
        }
    }
    if (idx < NE) {
        int a = idx_at(ei, 2*idx,   g_ed64);
        int b = idx_at(ei, 2*idx+1, g_ed64);
        atomicAdd(&g_deg[a], 1);
        atomicAdd(&g_deg[b], 1);
    }
}

// --------- scan (block 0) + cfg terms (blocks 1,2) + frag prep (3..30) --------
__global__ void k_scan_cfg(const float* __restrict__ cf, const float* __restrict__ ws0,
                           const float* __restrict__ wn0,
                           const float* __restrict__ ws, const float* __restrict__ wnn,
                           const float* __restrict__ skw) {
    int b = blockIdx.x;
    if (b == 0) {
        __shared__ int s[1024];
        int t = threadIdx.x;
        const int CH = 5;
        int base = t * CH;
        int v[CH]; int tot = 0;
        #pragma unroll
        for (int i = 0; i < CH; i++) {
            int idx = base + i;
            v[i] = (idx < NN) ? g_deg[idx] : 0;
            tot += v[i];
        }
        s[t] = tot; __syncthreads();
        for (int ofs = 1; ofs < 1024; ofs <<= 1) {
            int val = s[t];
            int add = (t >= ofs) ? s[t - ofs] : 0;
            __syncthreads();
            s[t] = val + add;
            __syncthreads();
        }
        int run = s[t] - tot;
        #pragma unroll
        for (int i = 0; i < CH; i++) {
            int idx = base + i;
            if (idx < NN) { g_off[idx] = run; run += v[i]; }
        }
        if (t == 1023) g_off[NN] = s[1023];
    } else if (b <= 2) {
        int idx = (b - 1) * 1024 + threadIdx.x;
        if (idx >= NC*HD) return;
        int c = idx >> 6, k = idx & 63;
        float s1 = 0.0f, s0v = 0.0f;
        #pragma unroll
        for (int d = 0; d < CFD; d++) {
            float cv = cf[c*CFD + d];
            float a  = ws0[(XND + d)*HD + k];
            float bq = wn0[(XND + d)*HD + k];
            s0v += cv * a;
            s1  += cv * (a + bq);
        }
        g_t0[idx] = s0v;
        g_t1[idx] = s1;
    } else if (b <= 14) {                     // g_fragF: 12 blocks x 1024
        int idx = (b - 3) * 1024 + threadIdx.x;
        int m = idx >> 12, i = idx & 4095;
        const float* W = (m == 0) ? ws : (m == 1) ? wnn : skw;
        g_fragF[idx] = frag_of(W, i);
    } else {                                   // g_fragL: 16 blocks x 1024
        int idx = (b - 15) * 1024 + threadIdx.x;
        int m = idx >> 12, i = idx & 4095;
        const float* W = (m == 0) ? (ws + HD*HD) : (m == 1) ? (wnn + HD*HD)
                        : (m == 2) ? (skw + HD*HD) : (skw + 2*HD*HD);
        g_fragL[idx] = frag_of(W, i);
    }
}

__global__ void k_fill(const void* __restrict__ ei) {
    int t = blockIdx.x * blockDim.x + threadIdx.x;
    if (t >= NE) return;
    int a = idx_at(ei, 2*t,   g_ed64);
    int b = idx_at(ei, 2*t+1, g_ed64);
    int pa = g_off[a] + atomicAdd(&g_cur[a], 1); g_adj[pa] = b;
    int pb = g_off[b] + atomicAdd(&g_cur[b], 1); g_adj[pb] = a;
}

// ---------------- layer-0 per-node GEMM (32-node tiles) ------------------------
__global__ void __launch_bounds__(256) k_pernode2(const float* __restrict__ ws0,
                                                  const float* __restrict__ wn0,
                                                  const float* __restrict__ b0) {
    extern __shared__ float sm[];
    float* ws0s = sm;
    float* wn0s = sm + 9472;
    float* xs   = sm + 18944;
    float* as_  = sm + 23680;
    int t = threadIdx.x;
    int tile = blockIdx.x;
    for (int i = t; i < XND*HD; i += 256) { ws0s[i] = ws0[i]; wn0s[i] = wn0[i]; }
    for (int i = t; i < 32*37; i += 256) {
        int s = i / 37, q = i % 37;
        int node = tile*32 + s;
        float4 xv = make_float4(0,0,0,0);
        float4 acc = make_float4(0,0,0,0);
        if (node < NN) {
            xv = ((const float4*)g_xn)[node*37 + q];
            int s0 = g_off[node], e0 = g_off[node+1];
            float inv = 1.0f / fmaxf((float)(e0 - s0), 1.0f);
            for (int j = s0; j < e0; j++) {
                float4 v = ((const float4*)g_xn)[g_adj[j]*37 + q];
                acc.x += v.x; acc.y += v.y; acc.z += v.z; acc.w += v.w;
            }
            acc.x *= inv; acc.y *= inv; acc.z *= inv; acc.w *= inv;
        }
        ((float4*)xs)[i] = xv;
        ((float4*)as_)[i] = acc;
    }
    __syncthreads();

    int rg = t >> 4, cg = t & 15;
    float4 b4 = *(const float4*)(b0 + cg*4);
    ull acc[2][2];
    acc[0][0] = f2pack(b4.x, b4.y); acc[0][1] = f2pack(b4.z, b4.w);
    acc[1][0] = acc[0][0];          acc[1][1] = acc[0][1];

    for (int dc = 0; dc < XND; dc += 4) {
        float4 x0 = *(const float4*)(xs  + (rg*2+0)*XND + dc);
        float4 x1 = *(const float4*)(xs  + (rg*2+1)*XND + dc);
        float4 a0 = *(const float4*)(as_ + (rg*2+0)*XND + dc);
        float4 a1 = *(const float4*)(as_ + (rg*2+1)*XND + dc);
        #pragma unroll
        for (int i = 0; i < 4; i++) {
            const ull* w1p = (const ull*)(ws0s + (dc+i)*HD + cg*4);
            const ull* w2p = (const ull*)(wn0s + (dc+i)*HD + cg*4);
            ull w1lo = w1p[0], w1hi = w1p[1];
            ull w2lo = w2p[0], w2hi = w2p[1];
            {
                float hx = ((const float*)&x0)[i], ax = ((const float*)&a0)[i];
                ull hb = f2pack(hx,hx), ab = f2pack(ax,ax);
                acc[0][0] = fma2(hb, w1lo, acc[0][0]);
                acc[0][0] = fma2(ab, w2lo, acc[0][0]);
                acc[0][1] = fma2(hb, w1hi, acc[0][1]);
                acc[0][1] = fma2(ab, w2hi, acc[0][1]);
            }
            {
                float hx = ((const float*)&x1)[i], ax = ((const float*)&a1)[i];
                ull hb = f2pack(hx,hx), ab = f2pack(ax,ax);
                acc[1][0] = fma2(hb, w1lo, acc[1][0]);
                acc[1][0] = fma2(ab, w2lo, acc[1][0]);
                acc[1][1] = fma2(hb, w1hi, acc[1][1]);
                acc[1][1] = fma2(ab, w2hi, acc[1][1]);
            }
        }
    }
    #pragma unroll
    for (int n = 0; n < 2; n++) {
        int node = tile*32 + rg*2 + n;
        if (node < NN) {
            float2 lo = f2unpack(acc[n][0]), hi = f2unpack(acc[n][1]);
            ((float4*)(g_pernode + node*HD))[cg] = make_float4(lo.x, lo.y, hi.x, hi.y);
        }
    }
}

// =============== layer 1 (tensor core): gmem B-frags ==========================
// smem: hsb[2x2176] asb[2x2176] t1s[2048] bds[64] bps[64] = 10880 floats
__global__ void __launch_bounds__(256) k_layer_first(
        float* __restrict__ hnew, const float* __restrict__ bias,
        const float* __restrict__ skb0) {
    extern __shared__ float sm[];
    float* hsb = sm;
    float* asb = sm + 4352;
    float* t1s = sm + 8704;
    float* bds = sm + 10752;
    float* bps = sm + 10816;
    int t = threadIdx.x;
    for (int i = t; i < NC*HD; i += 256) t1s[i] = g_t1[i];
    if (t < HD) { bds[t] = bias[t]; bps[t] = skb0[t]; }
    __syncthreads();

    const unsigned* __restrict__ wsF = g_fragF;
    const unsigned* __restrict__ wnF = g_fragF + 4096;
    const unsigned* __restrict__ spF = g_fragF + 8192;

    int half = t >> 7, wt = t & 127;
    int lane = t & 31, w = wt >> 5;
    int g = lane >> 2, tg = lane & 3;
    int rg = wt >> 4, kq = wt & 15;
    float* hs = hsb + half*2176;
    float* as = asb + half*2176;
    float4 t1r[4];
    #pragma unroll
    for (int m = 0; m < 4; m++) t1r[m] = ((const float4*)t1s)[(rg + 8*m)*16 + kq];

    float poolp[2][2][4];
    #pragma unroll
    for (int mt = 0; mt < 2; mt++)
        #pragma unroll
        for (int nt = 0; nt < 2; nt++)
            #pragma unroll
            for (int e = 0; e < 4; e++) poolp[mt][nt][e] = 0.0f;

    const float4* pern4 = (const float4*)g_pernode;

    for (int base = blockIdx.x*2; base < NN; base += gridDim.x*2) {
        int node = base + half;
        BARH(half);
        int s0 = g_off[node], e0 = g_off[node+1];
        float inv = 1.0f / fmaxf((float)(e0 - s0), 1.0f);
        float4 pown = pern4[node*16 + kq];
        #pragma unroll
        for (int m = 0; m < 4; m++) {
            int c = rg + 8*m;
            float4 tsel = t1r[m];
            if (e0 == s0) tsel = ((const float4*)g_t0)[c*16 + kq];  // rare: gmem/L2
            float4 r = relu4(make_float4(pown.x + tsel.x, pown.y + tsel.y,
                                         pown.z + tsel.z, pown.w + tsel.w));
            *(float4*)(hs + c*STR + kq*4) = tf32f4(r);
        }
        float4 ga[4];
        #pragma unroll
        for (int m = 0; m < 4; m++) ga[m] = make_float4(0,0,0,0);
        int j = s0;
        for (; j + 4 <= e0; j += 4) {
            int i0 = g_adj[j], i1 = g_adj[j+1], i2 = g_adj[j+2], i3 = g_adj[j+3];
            float4 p0 = pern4[i0*16 + kq];
            float4 p1 = pern4[i1*16 + kq];
            float4 p2 = pern4[i2*16 + kq];
            float4 p3 = pern4[i3*16 + kq];
            #pragma unroll
            for (int m = 0; m < 4; m++) {
                float4 tt = t1r[m];
                ga[m].x += fmaxf(p0.x + tt.x, 0.f) + fmaxf(p1.x + tt.x, 0.f)
                         + fmaxf(p2.x + tt.x, 0.f) + fmaxf(p3.x + tt.x, 0.f);
                ga[m].y += fmaxf(p0.y + tt.y, 0.f) + fmaxf(p1.y + tt.y, 0.f)
                         + fmaxf(p2.y + tt.y, 0.f) + fmaxf(p3.y + tt.y, 0.f);
                ga[m].z += fmaxf(p0.z + tt.z, 0.f) + fmaxf(p1.z + tt.z, 0.f)
                         + fmaxf(p2.z + tt.z, 0.f) + fmaxf(p3.z + tt.z, 0.f);
                ga[m].w += fmaxf(p0.w + tt.w, 0.f) + fmaxf(p1.w + tt.w, 0.f)
                         + fmaxf(p2.w + tt.w, 0.f) + fmaxf(p3.w + tt.w, 0.f);
            }
        }
        for (; j < e0; j++) {
            float4 p = pern4[g_adj[j]*16 + kq];
            #pragma unroll
            for (int m = 0; m < 4; m++) {
                float4 tt = t1r[m];
                ga[m].x += fmaxf(p.x + tt.x, 0.f);
                ga[m].y += fmaxf(p.y + tt.y, 0.f);
                ga[m].z += fmaxf(p.z + tt.z, 0.f);
                ga[m].w += fmaxf(p.w + tt.w, 0.f);
            }
        }
        #pragma unroll
        for (int m = 0; m < 4; m++) {
            int c = rg + 8*m;
            ga[m].x *= inv; ga[m].y *= inv; ga[m].z *= inv; ga[m].w *= inv;
            *(float4*)(as + c*STR + kq*4) = tf32f4(ga[m]);
        }
        BARH(half);

        float accd[2][2][4], acck[2][2][4];
        #pragma unroll
        for (int mt = 0; mt < 2; mt++)
            #pragma unroll
            for (int nt = 0; nt < 2; nt++)
                #pragma unroll
                for (int e = 0; e < 4; e++) { accd[mt][nt][e] = 0.f; acck[mt][nt][e] = 0.f; }
        #pragma unroll
        for (int ks = 0; ks < 8; ks++) {
            int k0 = ks*8;
            unsigned ah[2][4], aa[2][4];
            #pragma unroll
            for (int mt = 0; mt < 2; mt++) {
                int r0 = mt*16 + g;
                ah[mt][0] = __float_as_uint(hs[(r0  )*STR + k0 + tg]);
                ah[mt][1] = __float_as_uint(hs[(r0+8)*STR + k0 + tg]);
                ah[mt][2] = __float_as_uint(hs[(r0  )*STR + k0 + tg + 4]);
                ah[mt][3] = __float_as_uint(hs[(r0+8)*STR + k0 + tg + 4]);
                aa[mt][0] = __float_as_uint(as[(r0  )*STR + k0 + tg]);
                aa[mt][1] = __float_as_uint(as[(r0+8)*STR + k0 + tg]);
                aa[mt][2] = __float_as_uint(as[(r0  )*STR + k0 + tg + 4]);
                aa[mt][3] = __float_as_uint(as[(r0+8)*STR + k0 + tg + 4]);
            }
            #pragma unroll
            for (int nt = 0; nt < 2; nt++) {
                int fi = (((w*2 + nt)*8 + ks)*32 + lane)*2;
                uint2 bs = *(const uint2*)(wsF + fi);
                uint2 bn = *(const uint2*)(wnF + fi);
                uint2 bp = *(const uint2*)(spF + fi);
                #pragma unroll
                for (int mt = 0; mt < 2; mt++) {
                    mma_tf32(accd[mt][nt], ah[mt], bs.x, bs.y);
                    mma_tf32(accd[mt][nt], aa[mt], bn.x, bn.y);
                    mma_tf32(acck[mt][nt], ah[mt], bp.x, bp.y);
                }
            }
        }
        #pragma unroll
        for (int mt = 0; mt < 2; mt++)
            #pragma unroll
            for (int nt = 0; nt < 2; nt++) {
                int col = w*16 + nt*8 + 2*tg;
                float b0v = bds[col], b1v = bds[col+1];
                int r0 = mt*16 + g;
                float2 v0 = make_float2(fmaxf(accd[mt][nt][0] + b0v, 0.f),
                                        fmaxf(accd[mt][nt][1] + b1v, 0.f));
                float2 v1 = make_float2(fmaxf(accd[mt][nt][2] + b0v, 0.f),
                                        fmaxf(accd[mt][nt][3] + b1v, 0.f));
                *(float2*)(hnew + (size_t)node*ROWLEN + r0*HD + col) = v0;
                *(float2*)(hnew + (size_t)node*ROWLEN + (r0+8)*HD + col) = v1;
                float p0 = bps[col], p1 = bps[col+1];
                poolp[mt][nt][0] += fmaxf(acck[mt][nt][0] + p0, 0.f);
                poolp[mt][nt][1] += fmaxf(acck[mt][nt][1] + p1, 0.f);
                poolp[mt][nt][2] += fmaxf(acck[mt][nt][2] + p0, 0.f);
                poolp[mt][nt][3] += fmaxf(acck[mt][nt][3] + p1, 0.f);
            }
    }
    // pool merge (scratch = hsb; node loop complete for both halves)
    __syncthreads();
    if (half == 1) {
        #pragma unroll
        for (int mt = 0; mt < 2; mt++)
            #pragma unroll
            for (int nt = 0; nt < 2; nt++)
                #pragma unroll
                for (int e = 0; e < 4; e++)
                    hsb[wt*16 + (mt*2+nt)*4 + e] = poolp[mt][nt][e];
    }
    __syncthreads();
    if (half == 0) {
        #pragma unroll
        for (int mt = 0; mt < 2; mt++)
            #pragma unroll
            for (int nt = 0; nt < 2; nt++) {
                int col = w*16 + nt*8 + 2*tg;
                #pragma unroll
                for (int e = 0; e < 4; e++) {
                    float v = poolp[mt][nt][e] + hsb[wt*16 + (mt*2+nt)*4 + e];
                    int c = mt*16 + g + ((e >= 2) ? 8 : 0);
                    int cc = col + (e & 1);
                    atomicAdd(&g_pool[c*POOLD + 0*HD + cc], v);
                }
            }
    }
}

// =============== layer 2 (tensor core): gmem B-frags ==========================
// smem: hsb[2x2176] asb[2x2176] bds[64] bps[64] bos[64] = 8896 floats
__global__ void __launch_bounds__(256) k_layer_last(
        const float* __restrict__ hold, const float* __restrict__ bias,
        const float* __restrict__ skbp, const float* __restrict__ skbo) {
    extern __shared__ float sm[];
    float* hsb = sm;
    float* asb = sm + 4352;
    float* bds = sm + 8704;
    float* bps = sm + 8768;
    float* bos = sm + 8832;
    int t = threadIdx.x;
    if (t < HD) { bds[t] = bias[t]; bps[t] = skbp[t]; bos[t] = skbo[t]; }
    __syncthreads();

    const unsigned* __restrict__ wsF = g_fragL;
    const unsigned* __restrict__ wnF = g_fragL + 4096;
    const unsigned* __restrict__ spF = g_fragL + 8192;
    const unsigned* __restrict__ soF = g_fragL + 12288;

    int half = t >> 7, wt = t & 127;
    int lane = t & 31, w = wt >> 5;
    int g = lane >> 2, tg = lane & 3;
    int rg = wt >> 4, kq = wt & 15;
    float* hs = hsb + half*2176;
    float* as = asb + half*2176;

    float poolp[2][2][4], poolo[2][2][4];
    #pragma unroll
    for (int mt = 0; mt < 2; mt++)
        #pragma unroll
        for (int nt = 0; nt < 2; nt++)
            #pragma unroll
            for (int e = 0; e < 4; e++) { poolp[mt][nt][e] = 0.f; poolo[mt][nt][e] = 0.f; }

    for (int base = blockIdx.x*2; base < NN; base += gridDim.x*2) {
        int node = base + half;
        BARH(half);
        int s0 = g_off[node], e0 = g_off[node+1];
        float inv = 1.0f / fmaxf((float)(e0 - s0), 1.0f);
        const float4* own = (const float4*)(hold + (size_t)node*ROWLEN);
        float4 hv[4];
        #pragma unroll
        for (int m = 0; m < 4; m++) hv[m] = own[(rg + 8*m)*16 + kq];
        #pragma unroll
        for (int m = 0; m < 4; m++)
            *(float4*)(hs + (rg + 8*m)*STR + kq*4) = tf32f4(hv[m]);
        float4 am[4];
        #pragma unroll
        for (int m = 0; m < 4; m++) am[m] = make_float4(0,0,0,0);
        int j = s0;
        for (; j + 4 <= e0; j += 4) {
            int i0 = g_adj[j], i1 = g_adj[j+1], i2 = g_adj[j+2], i3 = g_adj[j+3];
            const float4* r0 = (const float4*)(hold + (size_t)i0*ROWLEN);
            const float4* r1 = (const float4*)(hold + (size_t)i1*ROWLEN);
            const float4* r2 = (const float4*)(hold + (size_t)i2*ROWLEN);
            const float4* r3 = (const float4*)(hold + (size_t)i3*ROWLEN);
            #pragma unroll
            for (int m = 0; m < 4; m++) {
                int ofs = (rg + 8*m)*16 + kq;
                float4 v0 = r0[ofs], v1 = r1[ofs], v2 = r2[ofs], v3 = r3[ofs];
                am[m].x += (v0.x + v1.x) + (v2.x + v3.x);
                am[m].y += (v0.y + v1.y) + (v2.y + v3.y);
                am[m].z += (v0.z + v1.z) + (v2.z + v3.z);
                am[m].w += (v0.w + v1.w) + (v2.w + v3.w);
            }
        }
        for (; j < e0; j++) {
            const float4* row = (const float4*)(hold + (size_t)g_adj[j]*ROWLEN);
            #pragma unroll
            for (int m = 0; m < 4; m++) {
                float4 v = row[(rg + 8*m)*16 + kq];
                am[m].x += v.x; am[m].y += v.y; am[m].z += v.z; am[m].w += v.w;
            }
        }
        #pragma unroll
        for (int m = 0; m < 4; m++) {
            int c = rg + 8*m;
            am[m].x *= inv; am[m].y *= inv; am[m].z *= inv; am[m].w *= inv;
            *(float4*)(as + c*STR + kq*4) = tf32f4(am[m]);
        }
        BARH(half);

        float accd[2][2][4], acck[2][2][4];
        #pragma unroll
        for (int mt = 0; mt < 2; mt++)
            #pragma unroll
            for (int nt = 0; nt < 2; nt++)
                #pragma unroll
                for (int e = 0; e < 4; e++) { accd[mt][nt][e] = 0.f; acck[mt][nt][e] = 0.f; }
        #pragma unroll
        for (int ks = 0; ks < 8; ks++) {
            int k0 = ks*8;
            unsigned ah[2][4], aa[2][4];
            #pragma unroll
            for (int mt = 0; mt < 2; mt++) {
                int r0 = mt*16 + g;
                ah[mt][0] = __float_as_uint(hs[(r0  )*STR + k0 + tg]);
                ah[mt][1] = __float_as_uint(hs[(r0+8)*STR + k0 + tg]);
                ah[mt][2] = __float_as_uint(hs[(r0  )*STR + k0 + tg + 4]);
                ah[mt][3] = __float_as_uint(hs[(r0+8)*STR + k0 + tg + 4]);
                aa[mt][0] = __float_as_uint(as[(r0  )*STR + k0 + tg]);
                aa[mt][1] = __float_as_uint(as[(r0+8)*STR + k0 + tg]);
                aa[mt][2] = __float_as_uint(as[(r0  )*STR + k0 + tg + 4]);
                aa[mt][3] = __float_as_uint(as[(r0+8)*STR + k0 + tg + 4]);
            }
            #pragma unroll
            for (int nt = 0; nt < 2; nt++) {
                int fi = (((w*2 + nt)*8 + ks)*32 + lane)*2;
                uint2 bs = *(const uint2*)(wsF + fi);
                uint2 bn = *(const uint2*)(wnF + fi);
                uint2 bp = *(const uint2*)(spF + fi);
                #pragma unroll
                for (int mt = 0; mt < 2; mt++) {
                    mma_tf32(accd[mt][nt], ah[mt], bs.x, bs.y);
                    mma_tf32(accd[mt][nt], aa[mt], bn.x, bn.y);
                    mma_tf32(acck[mt][nt], ah[mt], bp.x, bp.y);
                }
            }
        }
        BARH(half);
        #pragma unroll
        for (int mt = 0; mt < 2; mt++)
            #pragma unroll
            for (int nt = 0; nt < 2; nt++) {
                int col = w*16 + nt*8 + 2*tg;
                float b0v = bds[col], b1v = bds[col+1];
                int r0 = mt*16 + g;
                *(float2*)(hs + r0*STR + col) =
                    make_float2(tf32f(fmaxf(accd[mt][nt][0] + b0v, 0.f)),
                                tf32f(fmaxf(accd[mt][nt][1] + b1v, 0.f)));
                *(float2*)(hs + (r0+8)*STR + col) =
                    make_float2(tf32f(fmaxf(accd[mt][nt][2] + b0v, 0.f)),
                                tf32f(fmaxf(accd[mt][nt][3] + b1v, 0.f)));
                float p0 = bps[col], p1 = bps[col+1];
                poolp[mt][nt][0] += fmaxf(acck[mt][nt][0] + p0, 0.f);
                poolp[mt][nt][1] += fmaxf(acck[mt][nt][1] + p1, 0.f);
                poolp[mt][nt][2] += fmaxf(acck[mt][nt][2] + p0, 0.f);
                poolp[mt][nt][3] += fmaxf(acck[mt][nt][3] + p1, 0.f);
            }
        BARH(half);

        float acco[2][2][4];
        #pragma unroll
        for (int mt = 0; mt < 2; mt++)
            #pragma unroll
            for (int nt = 0; nt < 2; nt++)
                #pragma unroll
                for (int e = 0; e < 4; e++) acco[mt][nt][e] = 0.f;
        #pragma unroll
        for (int ks = 0; ks < 8; ks++) {
            int k0 = ks*8;
            unsigned ah[2][4];
            #pragma unroll
            for (int mt = 0; mt < 2; mt++) {
                int r0 = mt*16 + g;
                ah[mt][0] = __float_as_uint(hs[(r0  )*STR + k0 + tg]);
                ah[mt][1] = __float_as_uint(hs[(r0+8)*STR + k0 + tg]);
                ah[mt][2] = __float_as_uint(hs[(r0  )*STR + k0 + tg + 4]);
                ah[mt][3] = __float_as_uint(hs[(r0+8)*STR + k0 + tg + 4]);
            }
            #pragma unroll
            for (int nt = 0; nt < 2; nt++) {
                int fi = (((w*2 + nt)*8 + ks)*32 + lane)*2;
                uint2 bo = *(const uint2*)(soF + fi);
                #pragma unroll
                for (int mt = 0; mt < 2; mt++)
                    mma_tf32(acco[mt][nt], ah[mt], bo.x, bo.y);
            }
        }
        #pragma unroll
        for (int mt = 0; mt < 2; mt++)
            #pragma unroll
            for (int nt = 0; nt < 2; nt++) {
                int col = w*16 + nt*8 + 2*tg;
                float p0 = bos[col], p1 = bos[col+1];
                poolo[mt][nt][0] += fmaxf(acco[mt][nt][0] + p0, 0.f);
                poolo[mt][nt][1] += fmaxf(acco[mt][nt][1] + p1, 0.f);
                poolo[mt][nt][2] += fmaxf(acco[mt][nt][2] + p0, 0.f);
                poolo[mt][nt][3] += fmaxf(acco[mt][nt][3] + p1, 0.f);
            }
    }
    // pool merge + atomics (scratch = hsb)
    __syncthreads();
    if (half == 1) {
        #pragma unroll
        for (int mt = 0; mt < 2; mt++)
            #pragma unroll
            for (int nt = 0; nt < 2; nt++)
                #pragma unroll
                for (int e = 0; e < 4; e++) {
                    hsb[wt*32 + (mt*2+nt)*4 + e] = poolp[mt][nt][e];
                    hsb[wt*32 + 16 + (mt*2+nt)*4 + e] = poolo[mt][nt][e];
                }
    }
    __syncthreads();
    if (half == 0) {
        #pragma unroll
        for (int mt = 0; mt < 2; mt++)
            #pragma unroll
            for (int nt = 0; nt < 2; nt++) {
                int col = w*16 + nt*8 + 2*tg;
                #pragma unroll
                for (int e = 0; e < 4; e++) {
                    int c = mt*16 + g + ((e >= 2) ? 8 : 0);
                    int cc = col + (e & 1);
                    float v = poolp[mt][nt][e] + hsb[wt*32 + (mt*2+nt)*4 + e];
                    atomicAdd(&g_pool[c*POOLD + 1*HD + cc], v);
                    float u = poolo[mt][nt][e] + hsb[wt*32 + 16 + (mt*2+nt)*4 + e];
                    atomicAdd(&g_pool[c*POOLD + 2*HD + cc], u);
                }
            }
    }
}

// ---------------- final MLP ----------------------------------------------------
__global__ void k_mlp(const float* __restrict__ p1w, const float* __restrict__ p1b,
                      const float* __restrict__ p2w, const float* __restrict__ p2b,
                      const float* __restrict__ p3w, const float* __restrict__ p3b,
                      float* __restrict__ out) {
    int c = blockIdx.x;
    int t = threadIdx.x;  // 128
    __shared__ float pr[POOLD], y1[128], y2[64];
    for (int i = t; i < POOLD; i += 128) pr[i] = g_pool[c*POOLD + i];
    __syncthreads();
    float s = p1b[t];
    #pragma unroll 4
    for (int d = 0; d < POOLD; d++) s += pr[d] * p1w[d*128 + t];
    y1[t] = fmaxf(s, 0.f);
    __syncthreads();
    if (t < 64) {
        float s2 = p2b[t];
        #pragma unroll 4
        for (int d = 0; d < 128; d++) s2 += y1[d] * p2w[d*64 + t];
        y2[t] = fmaxf(s2, 0.f);
    }
    __syncthreads();
    if (t == 0) {
        float s3 = p3b[0];
        for (int d = 0; d < 64; d++) s3 += y2[d] * p3w[d];
        out[c] = s3;
    }
}

// ---------------- launch -------------------------------------------------------
extern "C" void kernel_launch(void* const* d_in, const int* in_sizes, int n_in,
                              void* d_out, int out_size) {
    const float* nf     = (const float*)d_in[0];
    const void*  opc    = d_in[1];
    const void*  ei     = d_in[2];
    const float* cf     = (const float*)d_in[3];
    const float* op_emb = (const float*)d_in[4];
    const float* ws0    = (const float*)d_in[5];
    const float* wn0    = (const float*)d_in[6];
    const float* b0     = (const float*)d_in[7];
    const float* ws     = (const float*)d_in[8];
    const float* wnn    = (const float*)d_in[9];
    const float* bb     = (const float*)d_in[10];
    const float* skw    = (const float*)d_in[11];
    const float* skb    = (const float*)d_in[12];
    const float* p1w    = (const float*)d_in[13];
    const float* p1b    = (const float*)d_in[14];
    const float* p2w    = (const float*)d_in[15];
    const float* p2b    = (const float*)d_in[16];
    const float* p3w    = (const float*)d_in[17];
    const float* p3b    = (const float*)d_in[18];
    float* out = (float*)d_out;

    const int SMEM_LF = 10880 * (int)sizeof(float);  // 43520 B
    const int SMEM_LL = 8896  * (int)sizeof(float);  // 35584 B
    const int SMEM_PN = 28416 * (int)sizeof(float);  // 113664 B
    cudaFuncSetAttribute(k_layer_first,
                         cudaFuncAttributeMaxDynamicSharedMemorySize, SMEM_LF);
    cudaFuncSetAttribute(k_layer_last,
                         cudaFuncAttributeMaxDynamicSharedMemorySize, SMEM_LL);
    cudaFuncSetAttribute(k_pernode2,
                         cudaFuncAttributeMaxDynamicSharedMemorySize, SMEM_PN);

    float* ph1 = nullptr;
    cudaGetSymbolAddress((void**)&ph1, g_h1);

    k_pre<<<32, 256>>>(opc, ei);
    k_xn_deg<<<(NN*XND + 255)/256, 256>>>(nf, opc, op_emb, ei);
    k_scan_cfg<<<31, 1024>>>(cf, ws0, wn0, ws, wnn, skw);
    k_fill<<<(NE + 255)/256, 256>>>(ei);
    k_pernode2<<<157, 256, SMEM_PN>>>(ws0, wn0, b0);
    k_layer_first<<<592, 256, SMEM_LF>>>(ph1, bb, skb);
    k_layer_last<<<592, 256, SMEM_LL>>>(ph1, bb + HD, skb + HD, skb + 2*HD);
    k_mlp<<<32, 128>>>(p1w, p1b, p2w, p2b, p3w, p3b, out);
}